// round 3
// baseline (speedup 1.0000x reference)
#include <cuda_runtime.h>
#include <cstdint>

#define NCOLS   2048
#define THREADS 512
#define KSEL    1024
#define WLOW   (-0.12f)
#define WHIGH  ( 0.12f)

// order-preserving float -> uint key (ascending)
__device__ __forceinline__ unsigned f2u(float f) {
    unsigned u = __float_as_uint(f);
    return (u & 0x80000000u) ? ~u : (u | 0x80000000u);
}

__global__ void __launch_bounds__(THREADS)
ktakesall_kernel(const float* __restrict__ g, float* __restrict__ out) {
    __shared__ unsigned s_cand[NCOLS];   // candidate keys
    __shared__ int s_cntLo;              // # elements < WLOW
    __shared__ int s_nCand;              // # candidates in window
    __shared__ unsigned s_T;             // threshold key (rank k-1)
    __shared__ int s_zeroEq;             // how many ==T to zero (index order)
    __shared__ int s_wscan[16];          // per-warp equality counts / exclusive scan

    const int tid  = threadIdx.x;
    const int lane = tid & 31;
    const int wid  = tid >> 5;
    const size_t rowoff = (size_t)blockIdx.x * NCOLS;

    // ---- load row (vectorized, 4 elems/thread, contiguous per thread) ----
    float4 v = reinterpret_cast<const float4*>(g + rowoff)[tid];
    float xv[4] = {v.x, v.y, v.z, v.w};
    unsigned key[4];
#pragma unroll
    for (int j = 0; j < 4; j++) key[j] = f2u(xv[j]);

    if (tid == 0) { s_cntLo = 0; s_nCand = 0; }
    __syncthreads();

    // ---- phase 1: count below-window, compact in-window candidates ----
    int cLo = 0;
    bool win[4];
#pragma unroll
    for (int j = 0; j < 4; j++) {
        bool lo = xv[j] < WLOW;
        cLo += lo ? 1 : 0;
        win[j] = (!lo) && (xv[j] <= WHIGH);
    }
    {
        int wc = __reduce_add_sync(0xffffffffu, cLo);
        if (lane == 0) atomicAdd(&s_cntLo, wc);
    }
#pragma unroll
    for (int j = 0; j < 4; j++) {
        unsigned m = __ballot_sync(0xffffffffu, win[j]);
        int base = 0;
        if (lane == 0) base = atomicAdd(&s_nCand, __popc(m));
        base = __shfl_sync(0xffffffffu, base, 0);
        if (win[j]) s_cand[base + __popc(m & ((1u << lane) - 1u))] = key[j];
    }
    __syncthreads();

    int cntLo = s_cntLo;
    int nC    = s_nCand;
    bool ok = (cntLo <= KSEL - 1) && (KSEL - 1 < cntLo + nC);
    if (!ok) {
        // exact fallback: all 2048 elements become candidates (rare: ~1e-5/row)
        __syncthreads();
#pragma unroll
        for (int j = 0; j < 4; j++) s_cand[tid * 4 + j] = key[j];
        __syncthreads();
        cntLo = 0;
        nC = NCOLS;
    }

    // ---- phase 2: warp 0 exact radix bisection for rank r among candidates ----
    if (tid < 32) {
        const int r = (KSEL - 1) - cntLo;   // 0-based rank within candidates
        unsigned prefix = 0;
        int candLess = 0;
        if (nC <= 256) {
            unsigned ck[8];
#pragma unroll
            for (int i = 0; i < 8; i++) {
                int idx = lane + i * 32;
                ck[i] = (idx < nC) ? s_cand[idx] : 0xFFFFFFFFu;
            }
#pragma unroll
            for (int b = 31; b >= 0; --b) {
                unsigned t = prefix | (1u << b);
                int c = 0;
#pragma unroll
                for (int i = 0; i < 8; i++) c += (ck[i] < t) ? 1 : 0;
                c = __reduce_add_sync(0xffffffffu, c);
                if (c <= r) prefix = t;
            }
            int c = 0;
#pragma unroll
            for (int i = 0; i < 8; i++) c += (ck[i] < prefix) ? 1 : 0;
            candLess = __reduce_add_sync(0xffffffffu, c);
        } else {
            for (int b = 31; b >= 0; --b) {
                unsigned t = prefix | (1u << b);
                int c = 0;
                for (int i = lane; i < nC; i += 32) c += (s_cand[i] < t) ? 1 : 0;
                c = __reduce_add_sync(0xffffffffu, c);
                if (c <= r) prefix = t;
            }
            int c = 0;
            for (int i = lane; i < nC; i += 32) c += (s_cand[i] < prefix) ? 1 : 0;
            candLess = __reduce_add_sync(0xffffffffu, c);
        }
        if (lane == 0) {
            s_T = prefix;
            s_zeroEq = KSEL - (cntLo + candLess);  // >= 1 by construction
        }
    }
    __syncthreads();

    const unsigned T = s_T;
    const int zq = s_zeroEq;

    // ---- phase 3: index-order rank of elements equal to T (block scan) ----
    int eq[4];
    int eqc = 0;
#pragma unroll
    for (int j = 0; j < 4; j++) { eq[j] = (key[j] == T) ? 1 : 0; eqc += eq[j]; }

    int incl = eqc;
#pragma unroll
    for (int o = 1; o < 32; o <<= 1) {
        int t = __shfl_up_sync(0xffffffffu, incl, o);
        if (lane >= o) incl += t;
    }
    if (lane == 31) s_wscan[wid] = incl;
    __syncthreads();
    if (tid < 32) {
        int vv = (lane < 16) ? s_wscan[lane] : 0;
        int orig = vv;
#pragma unroll
        for (int o = 1; o < 32; o <<= 1) {
            int t = __shfl_up_sync(0xffffffffu, vv, o);
            if (lane >= o) vv += t;
        }
        if (lane < 16) s_wscan[lane] = vv - orig;  // exclusive across warps
    }
    __syncthreads();

    int rr = s_wscan[wid] + (incl - eqc);  // equals before my first element

    // ---- phase 4: write output ----
    float res[4];
#pragma unroll
    for (int j = 0; j < 4; j++) {
        bool z = (key[j] < T) || (eq[j] && (rr < zq));
        res[j] = z ? 0.0f : xv[j];
        rr += eq[j];
    }
    float4 o4;
    o4.x = res[0]; o4.y = res[1]; o4.z = res[2]; o4.w = res[3];
    reinterpret_cast<float4*>(out + rowoff)[tid] = o4;
}

extern "C" void kernel_launch(void* const* d_in, const int* in_sizes, int n_in,
                              void* d_out, int out_size) {
    const float* g = (const float*)d_in[0];
    float* out = (float*)d_out;
    const int rows = in_sizes[0] / NCOLS;   // 32768
    ktakesall_kernel<<<rows, THREADS>>>(g, out);
}

// round 4
// speedup vs baseline: 2.0770x; 2.0770x over previous
#include <cuda_runtime.h>
#include <cstdint>

#define NCOLS   2048
#define THREADS 512
#define KSEL    1024
#define WLOW   (-0.12f)
#define WHIGH  ( 0.12f)
#define SCALE  (254.0f / (WHIGH - WLOW))

// order-preserving float -> uint key (ascending)
__device__ __forceinline__ unsigned f2u(float f) {
    unsigned u = __float_as_uint(f);
    return (u & 0x80000000u) ? ~u : (u | 0x80000000u);
}
// inverse
__device__ __forceinline__ float u2f(unsigned k) {
    unsigned u = (k & 0x80000000u) ? (k ^ 0x80000000u) : ~k;
    return __uint_as_float(u);
}

__global__ void __launch_bounds__(THREADS, 4)
ktakesall_kernel(const float* __restrict__ g, float* __restrict__ out) {
    __shared__ int      s_hist[256];
    __shared__ int      s_cntLo, s_nC, s_B, s_prefix, s_nB, s_mode, s_zq;
    __shared__ unsigned s_T;
    __shared__ unsigned s_bb[32];
    __shared__ int      s_wscan[16];

    const int tid  = threadIdx.x;
    const int lane = tid & 31;
    const int wid  = tid >> 5;
    const size_t rowoff = (size_t)blockIdx.x * NCOLS;

    if (tid < 256) s_hist[tid] = 0;
    if (tid == 0) { s_cntLo = 0; s_nC = 0; s_nB = 0; s_B = -1; }

    // ---- load row: 4 contiguous elems/thread ----
    float4 v = reinterpret_cast<const float4*>(g + rowoff)[tid];
    float xv[4] = {v.x, v.y, v.z, v.w};
    unsigned key[4];
    unsigned bp = 0;           // 4 packed bucket ids (1 byte each)
    int cLo = 0, cW = 0;
#pragma unroll
    for (int j = 0; j < 4; j++) {
        key[j] = f2u(xv[j]);
        bool lo  = xv[j] < WLOW;
        bool win = (!lo) && (xv[j] <= WHIGH);
        cLo += lo;
        cW  += win;
        int b = (int)((xv[j] - WLOW) * SCALE);   // monotone non-decreasing map
        b = b < 0 ? 0 : (b > 254 ? 254 : b);
        if (!win) b = 255;                       // sentinel: not a candidate
        bp |= (unsigned)b << (8 * j);
    }
    __syncthreads();

    // ---- phase 1: histogram of in-window candidates + counters ----
#pragma unroll
    for (int j = 0; j < 4; j++) {
        int b = (bp >> (8 * j)) & 255;
        if (b != 255) atomicAdd(&s_hist[b], 1);
    }
    {
        int wLo = __reduce_add_sync(0xffffffffu, cLo);
        int wW  = __reduce_add_sync(0xffffffffu, cW);
        if (lane == 0) { atomicAdd(&s_cntLo, wLo); atomicAdd(&s_nC, wW); }
    }
    __syncthreads();

    const int cntLo = s_cntLo;
    const int rG = KSEL - 1;
    const bool ok = (cntLo <= rG) && (rG < cntLo + s_nC);

    // ---- phase 2a: warp 0 scans histogram, finds bucket B holding rank ----
    if (ok && wid == 0) {
        const int r = rG - cntLo;
        int h[8]; int ls = 0;
#pragma unroll
        for (int i = 0; i < 8; i++) { h[i] = s_hist[lane * 8 + i]; ls += h[i]; }
        int inc = ls;
#pragma unroll
        for (int o = 1; o < 32; o <<= 1) {
            int t = __shfl_up_sync(0xffffffffu, inc, o);
            if (lane >= o) inc += t;
        }
        int base = inc - ls;
        if (r >= base && r < inc) {              // exactly one lane
            int p = base, B = -1;
#pragma unroll
            for (int i = 0; i < 8; i++) {
                if (B < 0) {
                    if (r < p + h[i]) B = lane * 8 + i;
                    else p += h[i];
                }
            }
            s_B = B; s_prefix = p;
        }
    }
    __syncthreads();

    // ---- phase 2b: gather bucket-B keys (expected 1-3) ----
    const int B = s_B;
#pragma unroll
    for (int j = 0; j < 4; j++) {
        bool hit = (((bp >> (8 * j)) & 255) == (unsigned)B);
        unsigned m = __ballot_sync(0xffffffffu, hit);
        if (m) {
            int base;
            if (lane == 0) base = atomicAdd(&s_nB, __popc(m));
            base = __shfl_sync(0xffffffffu, base, 0);
            if (hit) {
                int pos = base + __popc(m & ((1u << lane) - 1u));
                if (pos < 32) s_bb[pos] = key[j];
            }
        }
    }
    __syncthreads();

    // ---- phase 2c: warp 0 exact select within bucket (expected 1 iter) ----
    if (wid == 0) {
        const int nB = s_nB;
        if (ok && B >= 0 && nB > 0 && nB <= 32) {
            const int rb = (rG - cntLo) - s_prefix;   // 0-based rank in bucket
            unsigned kk = (lane < nB) ? s_bb[lane] : 0xFFFFFFFFu;
            int acc = 0; unsigned T = 0; int E = 0;
            while (true) {
                unsigned m = __reduce_min_sync(0xffffffffu, kk);
                int c = __popc(__ballot_sync(0xffffffffu, kk == m));
                if (acc + c > rb) { T = m; E = c; break; }
                acc += c;
                if (kk == m) kk = 0xFFFFFFFFu;
            }
            if (lane == 0) {
                int zq = KSEL - (cntLo + s_prefix + acc);  // #equals to zero
                s_T = T; s_zq = zq;
                s_mode = (zq == E) ? 0 : 1;    // 0: zero all <=T (no scan needed)
            }
        } else if (lane == 0) {
            s_mode = 2;                         // rare fallback
        }
    }
    __syncthreads();

    // ---- rare exact fallback: block-wide 32-bit radix bisection ----
    if (s_mode == 2) {
        if (tid < 34) s_hist[tid] = 0;          // reuse as per-bit counters
        __syncthreads();
        unsigned prefix = 0;
        for (int b = 31; b >= 0; --b) {
            unsigned t = prefix | (1u << b);
            int c = 0;
#pragma unroll
            for (int j = 0; j < 4; j++) c += (key[j] < t) ? 1 : 0;
            c = __reduce_add_sync(0xffffffffu, c);
            if (lane == 0) atomicAdd(&s_hist[b], c);
            __syncthreads();
            if (s_hist[b] <= rG) prefix = t;    // uniform decision
        }
        int c = 0, e = 0;
#pragma unroll
        for (int j = 0; j < 4; j++) { c += (key[j] < prefix); e += (key[j] == prefix); }
        c = __reduce_add_sync(0xffffffffu, c);
        e = __reduce_add_sync(0xffffffffu, e);
        if (lane == 0) { atomicAdd(&s_hist[32], c); atomicAdd(&s_hist[33], e); }
        __syncthreads();
        if (tid == 0) {
            int less = s_hist[32], eq = s_hist[33];
            int zq = KSEL - less;
            s_T = prefix; s_zq = zq;
            s_mode = (zq == eq) ? 0 : 1;
        }
        __syncthreads();
    }

    const unsigned T = s_T;
    const int mode = s_mode;

    if (mode == 0) {
        // common path: zero everything <= T (all equals zeroed)
#pragma unroll
        for (int j = 0; j < 4; j++)
            xv[j] = (key[j] <= T) ? 0.0f : u2f(key[j]);
    } else {
        // index-ordered tie-break among equals (block scan)
        const int zq = s_zq;
        int eq[4]; int eqc = 0;
#pragma unroll
        for (int j = 0; j < 4; j++) { eq[j] = (key[j] == T) ? 1 : 0; eqc += eq[j]; }
        int incl = eqc;
#pragma unroll
        for (int o = 1; o < 32; o <<= 1) {
            int t = __shfl_up_sync(0xffffffffu, incl, o);
            if (lane >= o) incl += t;
        }
        if (lane == 31) s_wscan[wid] = incl;
        __syncthreads();
        if (tid < 32) {
            int vv = (lane < 16) ? s_wscan[lane] : 0;
            int orig = vv;
#pragma unroll
            for (int o = 1; o < 32; o <<= 1) {
                int t = __shfl_up_sync(0xffffffffu, vv, o);
                if (lane >= o) vv += t;
            }
            if (lane < 16) s_wscan[lane] = vv - orig;
        }
        __syncthreads();
        int rr = s_wscan[wid] + (incl - eqc);
#pragma unroll
        for (int j = 0; j < 4; j++) {
            bool z = (key[j] < T) || (eq[j] && (rr < zq));
            xv[j] = z ? 0.0f : u2f(key[j]);
            rr += eq[j];
        }
    }

    float4 o4;
    o4.x = xv[0]; o4.y = xv[1]; o4.z = xv[2]; o4.w = xv[3];
    reinterpret_cast<float4*>(out + rowoff)[tid] = o4;
}

extern "C" void kernel_launch(void* const* d_in, const int* in_sizes, int n_in,
                              void* d_out, int out_size) {
    const float* g = (const float*)d_in[0];
    float* out = (float*)d_out;
    const int rows = in_sizes[0] / NCOLS;   // 32768
    ktakesall_kernel<<<rows, THREADS>>>(g, out);
}

// round 6
// speedup vs baseline: 2.2323x; 1.0748x over previous
#include <cuda_runtime.h>
#include <cstdint>

#define NCOLS   2048
#define THREADS 512
#define KSEL    1024
#define RG      (KSEL - 1)
// window [-0.12, 0.12] mapped to buckets 0..254:  t = (x + 0.12) * (254/0.24)
#define SCALEF  1058.3333333f
#define BIASF   127.0f
#define INF_F   __int_as_float(0x7f800000)
#define FULLM   0xffffffffu

// order-preserving float->uint key (fallback path only)
__device__ __forceinline__ unsigned f2u(float f) {
    unsigned u = __float_as_uint(f);
    return (u & 0x80000000u) ? ~u : (u | 0x80000000u);
}
__device__ __forceinline__ float u2f(unsigned k) {
    unsigned u = (k & 0x80000000u) ? (k ^ 0x80000000u) : ~k;
    return __uint_as_float(u);
}
__device__ __forceinline__ float wmin(float v) {
#pragma unroll
    for (int o = 16; o; o >>= 1) v = fminf(v, __shfl_xor_sync(FULLM, v, o));
    return v;
}

__global__ void __launch_bounds__(THREADS, 4)
ktakesall_kernel(const float* __restrict__ g, float* __restrict__ out) {
    __shared__ int   s_hist[256];
    __shared__ int   s_cnt, s_B, s_prefix, s_nB;
    __shared__ float s_bbf[32];
    __shared__ int   s_wscan[16];

    const int tid  = threadIdx.x;
    const int lane = tid & 31;
    const int wid  = tid >> 5;
    const size_t rowoff = (size_t)blockIdx.x * NCOLS;

    if (tid < 256) s_hist[tid] = 0;
    if (tid == 0) { s_cnt = 0; s_nB = 0; s_B = -1; s_prefix = 0; }

    // ---- load row: 4 contiguous elems/thread; fused window+bucket map ----
    float4 v = reinterpret_cast<const float4*>(g + rowoff)[tid];
    float xv[4] = {v.x, v.y, v.z, v.w};
    unsigned bp = 0;          // 4 packed bucket ids (255 = out of window)
    int cc = 0;               // cLo | cHi<<16
#pragma unroll
    for (int j = 0; j < 4; j++) {
        float t = fmaf(xv[j], SCALEF, BIASF);      // monotone map
        int   it = (int)t;                         // trunc; valid when t>=0
        bool  lo = t < 0.0f;
        bool  hi = t > 254.0f;
        cc += lo ? 1 : 0;
        cc += hi ? 0x10000 : 0;
        unsigned b = (lo || hi) ? 255u : (unsigned)it;
        bp |= b << (8 * j);
    }
    __syncthreads();                               // B1: smem init visible

    // ---- phase 1: candidate histogram + packed counters ----
#pragma unroll
    for (int j = 0; j < 4; j++) {
        unsigned b = (bp >> (8 * j)) & 255u;
        if (b != 255u) atomicAdd(&s_hist[b], 1);
    }
    {
        int w = __reduce_add_sync(FULLM, cc);
        if (lane == 0) atomicAdd(&s_cnt, w);
    }
    __syncthreads();                               // B2: hist + counts ready

    const int cnt   = s_cnt;
    const int cntLo = cnt & 0xffff;
    const int cntHi = cnt >> 16;
    const bool ok = (cntLo <= RG) && (RG < NCOLS - cntHi);

    // ---- phase 2a: warp 0 finds bucket B containing global rank RG ----
    if (ok && wid == 0) {
        const int r = RG - cntLo;
        int h[8]; int ls = 0;
#pragma unroll
        for (int i = 0; i < 8; i++) { h[i] = s_hist[lane * 8 + i]; ls += h[i]; }
        int inc = ls;
#pragma unroll
        for (int o = 1; o < 32; o <<= 1) {
            int t = __shfl_up_sync(FULLM, inc, o);
            if (lane >= o) inc += t;
        }
        int base = inc - ls;
        if (r >= base && r < inc) {                // exactly one lane
            int p = base, B = -1;
#pragma unroll
            for (int i = 0; i < 8; i++) {
                if (B < 0) {
                    if (r < p + h[i]) B = lane * 8 + i;
                    else p += h[i];
                }
            }
            s_B = B; s_prefix = p;
        }
    }
    __syncthreads();                               // B3: B broadcast

    // ---- phase 2b: gather bucket-B values (expected 1-3 in whole block) ----
    const int B = s_B;
    if (B >= 0) {
        unsigned mask = __vcmpeq4(bp, (unsigned)B * 0x01010101u);
        if (mask) {
#pragma unroll
            for (int j = 0; j < 4; j++) {
                if (mask & (0xFFu << (8 * j))) {
                    int p = atomicAdd(&s_nB, 1);
                    if (p < 32) s_bbf[p] = xv[j];
                }
            }
        }
    }
    __syncthreads();                               // B4: bucket gathered

    // ---- phase 2c: every warp redundantly selects exact threshold ----
    const int nB = s_nB;
    int mode; float Tf = 0.0f; int zq = 0;
    if (ok && B >= 0 && nB > 0 && nB <= 32) {
        const int rb = (RG - cntLo) - s_prefix;    // 0-based rank in bucket
        float kk = (lane < nB) ? s_bbf[lane] : INF_F;
        int acc = 0; float m; int c;
        while (true) {
            m = wmin(kk);
            c = __popc(__ballot_sync(FULLM, kk == m));
            if (acc + c > rb) break;
            acc += c;
            if (kk == m) kk = INF_F;
        }
        Tf = m;
        zq = rb - acc + 1;                         // #equals to zero, in [1,c]
        mode = (zq == c) ? 0 : 1;
    } else {
        mode = 2;
    }

    // ---- rare exact fallback: block-wide radix bisection on keys ----
    if (mode == 2) {
        unsigned key[4];
#pragma unroll
        for (int j = 0; j < 4; j++) key[j] = f2u(xv[j]);
        if (tid < 34) s_hist[tid] = 0;
        __syncthreads();
        unsigned prefix = 0;
        for (int b = 31; b >= 0; --b) {
            unsigned t = prefix | (1u << b);
            int c = 0;
#pragma unroll
            for (int j = 0; j < 4; j++) c += (key[j] < t) ? 1 : 0;
            c = __reduce_add_sync(FULLM, c);
            if (lane == 0) atomicAdd(&s_hist[b], c);
            __syncthreads();
            if (s_hist[b] <= RG) prefix = t;       // uniform decision
        }
        int c = 0, e = 0;
#pragma unroll
        for (int j = 0; j < 4; j++) { c += (key[j] < prefix); e += (key[j] == prefix); }
        c = __reduce_add_sync(FULLM, c);
        e = __reduce_add_sync(FULLM, e);
        if (lane == 0) { atomicAdd(&s_hist[32], c); atomicAdd(&s_hist[33], e); }
        __syncthreads();
        int less = s_hist[32], eq = s_hist[33];
        zq = KSEL - less;
        Tf = u2f(prefix);
        mode = (zq == eq) ? 0 : 1;
    }

    // ---- phase 3: write output ----
    if (mode == 0) {
        // common path: zero everything <= Tf
#pragma unroll
        for (int j = 0; j < 4; j++)
            xv[j] = (xv[j] <= Tf) ? 0.0f : xv[j];
    } else {
        // index-ordered tie-break among equals (block scan)
        int eq[4]; int eqc = 0;
#pragma unroll
        for (int j = 0; j < 4; j++) { eq[j] = (xv[j] == Tf) ? 1 : 0; eqc += eq[j]; }
        int incl = eqc;
#pragma unroll
        for (int o = 1; o < 32; o <<= 1) {
            int t = __shfl_up_sync(FULLM, incl, o);
            if (lane >= o) incl += t;
        }
        if (lane == 31) s_wscan[wid] = incl;
        __syncthreads();
        if (tid < 32) {
            int vv = (lane < 16) ? s_wscan[lane] : 0;
            int orig = vv;
#pragma unroll
            for (int o = 1; o < 32; o <<= 1) {
                int t = __shfl_up_sync(FULLM, vv, o);
                if (lane >= o) vv += t;
            }
            if (lane < 16) s_wscan[lane] = vv - orig;
        }
        __syncthreads();
        int rr = s_wscan[wid] + (incl - eqc);
#pragma unroll
        for (int j = 0; j < 4; j++) {
            bool z = (xv[j] < Tf) || (eq[j] && (rr < zq));
            xv[j] = z ? 0.0f : xv[j];
            rr += eq[j];
        }
    }

    float4 o4;
    o4.x = xv[0]; o4.y = xv[1]; o4.z = xv[2]; o4.w = xv[3];
    reinterpret_cast<float4*>(out + rowoff)[tid] = o4;
}

extern "C" void kernel_launch(void* const* d_in, const int* in_sizes, int n_in,
                              void* d_out, int out_size) {
    const float* g = (const float*)d_in[0];
    float* out = (float*)d_out;
    const int rows = in_sizes[0] / NCOLS;   // 32768
    ktakesall_kernel<<<rows, THREADS>>>(g, out);
}

// round 9
// speedup vs baseline: 3.1193x; 1.3973x over previous
#include <cuda_runtime.h>
#include <cstdint>

#define NCOLS   2048
#define THREADS 256
#define NPER    8          // elements per thread (2 x float4)
#define NWARPS  (THREADS / 32)
#define KSEL    1024
#define RG      (KSEL - 1)
// window [-0.12, 0.12] mapped to buckets 0..254:  t = (x + 0.12) * (254/0.24)
#define SCALEF  1058.3333333f
#define BIASF   127.0f
#define INF_F   __int_as_float(0x7f800000)
#define FULLM   0xffffffffu

// order-preserving float->uint key (fallback path only)
__device__ __forceinline__ unsigned f2u(float f) {
    unsigned u = __float_as_uint(f);
    return (u & 0x80000000u) ? ~u : (u | 0x80000000u);
}
__device__ __forceinline__ float u2f(unsigned k) {
    unsigned u = (k & 0x80000000u) ? (k ^ 0x80000000u) : ~k;
    return __uint_as_float(u);
}
__device__ __forceinline__ float wmin(float v) {
#pragma unroll
    for (int o = 16; o; o >>= 1) v = fminf(v, __shfl_xor_sync(FULLM, v, o));
    return v;
}

__global__ void __launch_bounds__(THREADS, 8)
ktakesall_kernel(const float* __restrict__ g, float* __restrict__ out) {
    __shared__ int   s_hist[256];
    __shared__ int   s_cnt, s_B, s_prefix, s_nB;
    __shared__ float s_bbf[32];
    __shared__ int   s_wscan[NWARPS];

    const int tid  = threadIdx.x;
    const int lane = tid & 31;
    const int wid  = tid >> 5;
    const size_t rowoff = (size_t)blockIdx.x * NCOLS;

    s_hist[tid] = 0;
    if (tid == 0) { s_cnt = 0; s_nB = 0; s_B = -1; s_prefix = 0; }

    // ---- load row: 8 contiguous elems/thread; fused window+bucket map ----
    const float4* gp = reinterpret_cast<const float4*>(g + rowoff) + tid * 2;
    float4 v0 = gp[0];
    float4 v1 = gp[1];
    float xv[NPER] = {v0.x, v0.y, v0.z, v0.w, v1.x, v1.y, v1.z, v1.w};
    unsigned bp[2] = {0, 0};   // 8 packed bucket ids (255 = out of window)
    int cc = 0;                // cLo | cHi<<16
#pragma unroll
    for (int j = 0; j < NPER; j++) {
        float t = fmaf(xv[j], SCALEF, BIASF);      // monotone map
        int   it = (int)t;                         // trunc; valid when t>=0
        bool  lo = t < 0.0f;
        bool  hi = t > 254.0f;
        cc += lo ? 1 : 0;
        cc += hi ? 0x10000 : 0;
        unsigned b = (lo || hi) ? 255u : (unsigned)it;
        bp[j >> 2] |= b << (8 * (j & 3));
    }
    __syncthreads();                               // B1: smem init visible

    // ---- phase 1: candidate histogram + packed counters ----
#pragma unroll
    for (int j = 0; j < NPER; j++) {
        unsigned b = (bp[j >> 2] >> (8 * (j & 3))) & 255u;
        if (b != 255u) atomicAdd(&s_hist[b], 1);
    }
    {
        int w = __reduce_add_sync(FULLM, cc);
        if (lane == 0) atomicAdd(&s_cnt, w);
    }
    __syncthreads();                               // B2: hist + counts ready

    const int cnt   = s_cnt;
    const int cntLo = cnt & 0xffff;
    const int cntHi = cnt >> 16;
    const bool ok = (cntLo <= RG) && (RG < NCOLS - cntHi);

    // ---- phase 2a: warp 0 finds bucket B containing global rank RG ----
    if (ok && wid == 0) {
        const int r = RG - cntLo;
        int h[8]; int ls = 0;
#pragma unroll
        for (int i = 0; i < 8; i++) { h[i] = s_hist[lane * 8 + i]; ls += h[i]; }
        int inc = ls;
#pragma unroll
        for (int o = 1; o < 32; o <<= 1) {
            int t = __shfl_up_sync(FULLM, inc, o);
            if (lane >= o) inc += t;
        }
        int base = inc - ls;
        if (r >= base && r < inc) {                // exactly one lane
            int p = base, B = -1;
#pragma unroll
            for (int i = 0; i < 8; i++) {
                if (B < 0) {
                    if (r < p + h[i]) B = lane * 8 + i;
                    else p += h[i];
                }
            }
            s_B = B; s_prefix = p;
        }
    }
    __syncthreads();                               // B3: B broadcast

    // ---- phase 2b: gather bucket-B values (expected 1-3 in whole block) ----
    const int B = s_B;
    if (B >= 0) {
        const unsigned pat = (unsigned)B * 0x01010101u;
        unsigned m0 = __vcmpeq4(bp[0], pat);
        unsigned m1 = __vcmpeq4(bp[1], pat);
        if (m0 | m1) {
#pragma unroll
            for (int j = 0; j < NPER; j++) {
                unsigned m = (j < 4) ? m0 : m1;
                if (m & (0xFFu << (8 * (j & 3)))) {
                    int p = atomicAdd(&s_nB, 1);
                    if (p < 32) s_bbf[p] = xv[j];
                }
            }
        }
    }
    __syncthreads();                               // B4: bucket gathered

    // ---- phase 2c: every warp redundantly selects exact threshold ----
    const int nB = s_nB;
    int mode; float Tf = 0.0f; int zq = 0;
    if (ok && B >= 0 && nB > 0 && nB <= 32) {
        const int rb = (RG - cntLo) - s_prefix;    // 0-based rank in bucket
        float kk = (lane < nB) ? s_bbf[lane] : INF_F;
        int acc = 0; float m; int c;
        while (true) {
            m = wmin(kk);
            c = __popc(__ballot_sync(FULLM, kk == m));
            if (acc + c > rb) break;
            acc += c;
            if (kk == m) kk = INF_F;
        }
        Tf = m;
        zq = rb - acc + 1;                         // #equals to zero, in [1,c]
        mode = (zq == c) ? 0 : 1;
    } else {
        mode = 2;
    }

    // ---- rare exact fallback: block-wide radix bisection on keys ----
    if (mode == 2) {
        unsigned key[NPER];
#pragma unroll
        for (int j = 0; j < NPER; j++) key[j] = f2u(xv[j]);
        if (tid < 34) s_hist[tid] = 0;
        __syncthreads();
        unsigned prefix = 0;
        for (int b = 31; b >= 0; --b) {
            unsigned t = prefix | (1u << b);
            int c = 0;
#pragma unroll
            for (int j = 0; j < NPER; j++) c += (key[j] < t) ? 1 : 0;
            c = __reduce_add_sync(FULLM, c);
            if (lane == 0) atomicAdd(&s_hist[b], c);
            __syncthreads();
            if (s_hist[b] <= RG) prefix = t;       // uniform decision
        }
        int c = 0, e = 0;
#pragma unroll
        for (int j = 0; j < NPER; j++) { c += (key[j] < prefix); e += (key[j] == prefix); }
        c = __reduce_add_sync(FULLM, c);
        e = __reduce_add_sync(FULLM, e);
        if (lane == 0) { atomicAdd(&s_hist[32], c); atomicAdd(&s_hist[33], e); }
        __syncthreads();
        int less = s_hist[32], eq = s_hist[33];
        zq = KSEL - less;
        Tf = u2f(prefix);
        mode = (zq == eq) ? 0 : 1;
    }

    // ---- phase 3: write output ----
    if (mode == 0) {
        // common path: zero everything <= Tf
#pragma unroll
        for (int j = 0; j < NPER; j++)
            xv[j] = (xv[j] <= Tf) ? 0.0f : xv[j];
    } else {
        // index-ordered tie-break among equals (block scan)
        int eq[NPER]; int eqc = 0;
#pragma unroll
        for (int j = 0; j < NPER; j++) { eq[j] = (xv[j] == Tf) ? 1 : 0; eqc += eq[j]; }
        int incl = eqc;
#pragma unroll
        for (int o = 1; o < 32; o <<= 1) {
            int t = __shfl_up_sync(FULLM, incl, o);
            if (lane >= o) incl += t;
        }
        if (lane == 31) s_wscan[wid] = incl;
        __syncthreads();
        if (tid < 32) {
            int vv = (lane < NWARPS) ? s_wscan[lane] : 0;
            int orig = vv;
#pragma unroll
            for (int o = 1; o < NWARPS; o <<= 1) {
                int t = __shfl_up_sync(FULLM, vv, o);
                if (lane >= o) vv += t;
            }
            if (lane < NWARPS) s_wscan[lane] = vv - orig;
        }
        __syncthreads();
        int rr = s_wscan[wid] + (incl - eqc);
#pragma unroll
        for (int j = 0; j < NPER; j++) {
            bool z = (xv[j] < Tf) || (eq[j] && (rr < zq));
            xv[j] = z ? 0.0f : xv[j];
            rr += eq[j];
        }
    }

    float4 o4a, o4b;
    o4a.x = xv[0]; o4a.y = xv[1]; o4a.z = xv[2]; o4a.w = xv[3];
    o4b.x = xv[4]; o4b.y = xv[5]; o4b.z = xv[6]; o4b.w = xv[7];
    float4* op = reinterpret_cast<float4*>(out + rowoff) + tid * 2;
    op[0] = o4a;
    op[1] = o4b;
}

extern "C" void kernel_launch(void* const* d_in, const int* in_sizes, int n_in,
                              void* d_out, int out_size) {
    const float* g = (const float*)d_in[0];
    float* out = (float*)d_out;
    const int rows = in_sizes[0] / NCOLS;   // 32768
    ktakesall_kernel<<<rows, THREADS>>>(g, out);
}